// round 7
// baseline (speedup 1.0000x reference)
#include <cuda_runtime.h>
#include <cuda_bf16.h>
#include <cstdint>
#include <cstddef>

#define NN   50000
#define NE   600000
#define NG   64
#define HID  128
#define OUTD 256

// ---------------- scratch (no allocation allowed) ----------------
__device__ float g_h[(size_t)NN * HID];
__device__ float g_hr[(size_t)NN * HID];   // h @ W1a  (per-layer)
__device__ float g_hc[(size_t)NN * HID];   // h @ W1b
__device__ float g_coord[NN * 3];
__device__ float g_deg[NN];
__device__ float g_magg[(size_t)NN * HID];
__device__ float g_cagg[NN * 3];
__device__ float g_pool[NG * HID];
__device__ float g_cnt[NG];
// bf16 weight images: [layer][wsel: 0=W2,1=Wc1][0=hi,1=lo][128 n x pitch136 k]
__device__ unsigned short g_wpack[3 * 2 * 2 * 17408];

__device__ __forceinline__ float silu_f(float x) { return x / (1.0f + __expf(-x)); }

// ---------------- bf16 split helpers ----------------
__device__ __forceinline__ void bf16_split2(float x, float y, uint32_t& hi, uint32_t& lo) {
    __nv_bfloat16 hx = __float2bfloat16(x);
    __nv_bfloat16 hy = __float2bfloat16(y);
    __nv_bfloat16 lx = __float2bfloat16(x - __bfloat162float(hx));
    __nv_bfloat16 ly = __float2bfloat16(y - __bfloat162float(hy));
    __nv_bfloat162 hp; hp.x = hx; hp.y = hy;
    __nv_bfloat162 lp; lp.x = lx; lp.y = ly;
    hi = *(uint32_t*)&hp;
    lo = *(uint32_t*)&lp;
}

// ---------------- bf16 mma.sync (works on compute_100; no arch-suffix features) ----
__device__ __forceinline__ void mma_bf16(float c[4], const uint32_t a[4],
                                         uint32_t b0, uint32_t b1) {
    asm volatile(
        "mma.sync.aligned.m16n8k16.row.col.f32.bf16.bf16.f32 "
        "{%0,%1,%2,%3}, {%4,%5,%6,%7}, {%8,%9}, {%0,%1,%2,%3};"
        : "+f"(c[0]), "+f"(c[1]), "+f"(c[2]), "+f"(c[3])
        : "r"(a[0]), "r"(a[1]), "r"(a[2]), "r"(a[3]), "r"(b0), "r"(b1));
}

// A/B smem pitch: 136 bf16 = 272 bytes (17*16B -> conflict-free fragment LDS)
#define PITCH_B 272

// 3-term GEMM: acc = Ahi*Bhi + Alo*Bhi + Ahi*Blo  (128x128x128, warp tile 32x64)
__device__ __forceinline__ void mma_gemm3(
    const char* sb, uint32_t aHi, uint32_t aLo, uint32_t bHi, uint32_t bLo,
    float acc[2][8][4], int mrow0, int ncol0, int lane)
{
#pragma unroll
    for (int mt = 0; mt < 2; mt++)
#pragma unroll
        for (int nt = 0; nt < 8; nt++)
#pragma unroll
            for (int j = 0; j < 4; j++) acc[mt][nt][j] = 0.0f;

    const int rb = lane >> 2;
    const int qb = (lane & 3) * 4;
#pragma unroll
    for (int term = 0; term < 3; term++) {
        const uint32_t aOff = (term == 1) ? aLo : aHi;
        const uint32_t bOff = (term == 2) ? bLo : bHi;
#pragma unroll
        for (int ks = 0; ks < 8; ks++) {
            uint32_t a[2][4];
#pragma unroll
            for (int mt = 0; mt < 2; mt++) {
                const char* ap = sb + aOff + (mrow0 + mt * 16 + rb) * PITCH_B + qb + ks * 32;
                a[mt][0] = *(const uint32_t*)ap;
                a[mt][1] = *(const uint32_t*)(ap + 8 * PITCH_B);
                a[mt][2] = *(const uint32_t*)(ap + 16);
                a[mt][3] = *(const uint32_t*)(ap + 8 * PITCH_B + 16);
            }
#pragma unroll
            for (int nt = 0; nt < 8; nt++) {
                const char* bp = sb + bOff + (ncol0 + nt * 8 + rb) * PITCH_B + qb + ks * 32;
                uint32_t b0 = *(const uint32_t*)bp;
                uint32_t b1 = *(const uint32_t*)(bp + 16);
                mma_bf16(acc[0][nt], a[0], b0, b1);
                mma_bf16(acc[1][nt], a[1], b0, b1);
            }
        }
    }
}

// ---------------- scalar FFMA2 path (node-side kernels) ----------------
__device__ __forceinline__ void fma2(unsigned long long& d,
                                     unsigned long long a, unsigned long long b) {
    asm("fma.rn.f32x2 %0, %1, %2, %0;" : "+l"(d) : "l"(a), "l"(b));
}
__device__ __forceinline__ unsigned long long pack2(float x) {
    unsigned long long r;
    asm("mov.b64 %0, {%1, %1};" : "=l"(r) : "f"(x));
    return r;
}
__device__ __forceinline__ void unpack2(unsigned long long v, float& lo, float& hi) {
    asm("mov.b64 {%0, %1}, %2;" : "=f"(lo), "=f"(hi) : "l"(v));
}

__device__ __forceinline__ void gemm_tile64(
    const float* __restrict__ sIn, int ldi,
    const float* __restrict__ gW, int K,
    float* __restrict__ sW, float acc[8][4])
{
    const int tid = threadIdx.x;
    const int tr  = tid >> 5;
    const int tc  = tid & 31;

    unsigned long long acc2[8][2];
#pragma unroll
    for (int i = 0; i < 8; i++) { acc2[i][0] = 0ull; acc2[i][1] = 0ull; }

    for (int k0 = 0; k0 + 32 <= K; k0 += 32) {
        __syncthreads();
#pragma unroll
        for (int j = 0; j < 4; j++) {
            int f  = tid + j * 256;
            int rw = f >> 5, cf = f & 31;
            *(float4*)&sW[rw * 128 + cf * 4] =
                __ldg(reinterpret_cast<const float4*>(&gW[(size_t)(k0 + rw) * 128 + cf * 4]));
        }
        __syncthreads();
#pragma unroll
        for (int k4 = 0; k4 < 32; k4 += 4) {
            float4 a[8];
#pragma unroll
            for (int i = 0; i < 8; i++)
                a[i] = *(const float4*)&sIn[(tr * 8 + i) * ldi + k0 + k4];
#pragma unroll
            for (int kk = 0; kk < 4; kk++) {
                const unsigned long long* wp =
                    (const unsigned long long*)&sW[(k4 + kk) * 128 + tc * 4];
                unsigned long long w0 = wp[0], w1 = wp[1];
#pragma unroll
                for (int i = 0; i < 8; i++) {
                    float av = (kk == 0) ? a[i].x : (kk == 1) ? a[i].y
                             : (kk == 2) ? a[i].z : a[i].w;
                    unsigned long long ap = pack2(av);
                    fma2(acc2[i][0], ap, w0);
                    fma2(acc2[i][1], ap, w1);
                }
            }
        }
    }
#pragma unroll
    for (int i = 0; i < 8; i++) {
        unpack2(acc2[i][0], acc[i][0], acc[i][1]);
        unpack2(acc2[i][1], acc[i][2], acc[i][3]);
    }
}

// ---------------- setup1: zero + copy coord + pack bf16 weight images ----------------
__global__ void setup1_kernel(const float* __restrict__ coord_in,
                              const float* __restrict__ ew2,
                              const float* __restrict__ ecw1)
{
    int idx = blockIdx.x * 256 + threadIdx.x;
    if (idx < NN)        g_deg[idx]  = 0.0f;
    if (idx < NG * HID)  g_pool[idx] = 0.0f;
    if (idx < NG)        g_cnt[idx]  = 0.0f;
    if (idx < NN * 3)    g_coord[idx] = coord_in[idx];
    if (idx < 3 * 2 * 16384) {
        int l = idx >> 15, rem = idx & 32767;
        int wsel = rem >> 14, pos = rem & 16383;
        int n = pos >> 7, k = pos & 127;
        const float* W = wsel ? (ecw1 + (size_t)l * 16384) : (ew2 + (size_t)l * 16384);
        float v = W[k * 128 + n];          // transpose: image row n = output col
        __nv_bfloat16 h = __float2bfloat16(v);
        __nv_bfloat16 lo = __float2bfloat16(v - __bfloat162float(h));
        unsigned short* baseH = g_wpack + (size_t)((l * 2 + wsel) * 2 + 0) * 17408;
        unsigned short* baseL = g_wpack + (size_t)((l * 2 + wsel) * 2 + 1) * 17408;
        baseH[n * 136 + k] = __bfloat16_as_ushort(h);
        baseL[n * 136 + k] = __bfloat16_as_ushort(lo);
    }
}

// ---------------- mega2: deg + cnt atomics + embed + zero layer0 agg ----------------
__global__ void mega2_kernel(const int* __restrict__ erow,
                             const int* __restrict__ batch,
                             const float* __restrict__ x,
                             const float* __restrict__ W,
                             const float* __restrict__ b)
{
    size_t idx = (size_t)blockIdx.x * 256 + threadIdx.x;
    if (idx < NE) atomicAdd(&g_deg[erow[idx]], 1.0f);
    if (idx < NN) atomicAdd(&g_cnt[batch[idx]], 1.0f);
    if (idx < NN * 3) g_cagg[idx] = 0.0f;
    if (idx < (size_t)NN * HID) {
        g_magg[idx] = 0.0f;
        int i = (int)(idx >> 7);
        int c = (int)(idx & 127);
        const float* xr = &x[i * 16];
        float a = b[c];
#pragma unroll
        for (int k = 0; k < 16; k++) a = fmaf(xr[k], W[k * 128 + c], a);
        g_h[idx] = a;
    }
}

__global__ void zero_layer_kernel() {
    size_t idx = (size_t)blockIdx.x * 256 + threadIdx.x;
    if (idx < (size_t)NN * HID) g_magg[idx] = 0.0f;
    if (idx < NN * 3)           g_cagg[idx] = 0.0f;
}

// ---------------- per-node precompute: g_hr = h@W1a, g_hc = h@W1b ----------------
#define HPRE_SMEM_F (64 * 132 + 32 * 128)

__global__ void __launch_bounds__(256) hpre_kernel(const float* __restrict__ W1)
{
    extern __shared__ float sm[];
    float* sH = sm;
    float* sW = sH + 64 * 132;

    const int tid = threadIdx.x;
    const int warp = tid >> 5, lane = tid & 31;
    const int n0 = blockIdx.x * 64;

    for (int i = warp; i < 64; i += 8) {
        int node = n0 + i;
        ((float4*)&sH[i * 132])[lane] = (node < NN)
            ? *(const float4*)&g_h[(size_t)node * 128 + lane * 4]
            : make_float4(0.f, 0.f, 0.f, 0.f);
    }

    const int tr = tid >> 5, tc = tid & 31;
    float acc[8][4];

    gemm_tile64(sH, 132, W1, 128, sW, acc);
#pragma unroll
    for (int i = 0; i < 8; i++) {
        int node = n0 + tr * 8 + i;
        if (node < NN)
            *(float4*)&g_hr[(size_t)node * 128 + tc * 4] =
                make_float4(acc[i][0], acc[i][1], acc[i][2], acc[i][3]);
    }
    __syncthreads();

    gemm_tile64(sH, 132, W1 + 128 * 128, 128, sW, acc);
#pragma unroll
    for (int i = 0; i < 8; i++) {
        int node = n0 + tr * 8 + i;
        if (node < NN)
            *(float4*)&g_hc[(size_t)node * 128 + tc * 4] =
                make_float4(acc[i][0], acc[i][1], acc[i][2], acc[i][3]);
    }
}

// ---------------- edge kernel (mma.sync bf16 3-term) ----------------
// smem byte layout
#define OFF_AHI  0                 // 128 x 272B
#define OFF_ALO  34816
#define OFF_BHI  69632
#define OFF_BLO  104448
#define OFF_SD   139264            // 128 x 4 floats
#define OFF_CW   141312            // 128 x 2 floats
#define OFF_B2   142336            // 128 floats
#define OFF_BC1  142848
#define OFF_WC2  143360
#define OFF_WR   143872
#define OFF_WE   144384
#define OFF_B1   144896
#define OFF_ROW  145408            // 128 ints
#define EDGE_SMEM_BYTES 145920

__global__ void __launch_bounds__(256, 1) edge_mma_kernel(
    const int* __restrict__ erow, const int* __restrict__ ecol,
    const float* __restrict__ eattr,
    const float* __restrict__ W1, const float* __restrict__ b1,
    const float* __restrict__ b2, const float* __restrict__ bc1,
    const float* __restrict__ Wc2, int layer)
{
    extern __shared__ char sb[];
    const int tid = threadIdx.x;
    const int wid = tid >> 5, lane = tid & 31;
    const int e0 = blockIdx.x * 128;

    float* sD  = (float*)(sb + OFF_SD);
    float* sCW = (float*)(sb + OFF_CW);
    float* sB2 = (float*)(sb + OFF_B2);
    float* sBC = (float*)(sb + OFF_BC1);
    float* sWC = (float*)(sb + OFF_WC2);
    float* sWR = (float*)(sb + OFF_WR);
    float* sWE = (float*)(sb + OFF_WE);
    float* sB1 = (float*)(sb + OFF_B1);
    int*   sRow = (int*)(sb + OFF_ROW);

    if (tid < 128) {
        sWR[tid] = __ldg(&W1[256 * 128 + tid]);
        sWE[tid] = __ldg(&W1[257 * 128 + tid]);
        sB1[tid] = __ldg(&b1[tid]);
        sB2[tid] = __ldg(&b2[tid]);
        sBC[tid] = __ldg(&bc1[tid]);
        sWC[tid] = __ldg(&Wc2[tid]);
    }

    // B images for GEMM2 (W2)
    {
        const uint4* srcH = (const uint4*)(g_wpack + (size_t)((layer * 2 + 0) * 2 + 0) * 17408);
        const uint4* srcL = (const uint4*)(g_wpack + (size_t)((layer * 2 + 0) * 2 + 1) * 17408);
        uint4* dstH = (uint4*)(sb + OFF_BHI);
        uint4* dstL = (uint4*)(sb + OFF_BLO);
        for (int j = tid; j < 2176; j += 256) { dstH[j] = __ldg(&srcH[j]); dstL[j] = __ldg(&srcL[j]); }
    }
    __syncthreads();

    // gather + m1 = silu(hr[row]+hc[col]+radial*wr+ea*we+b1) -> A_hi/A_lo (bf16)
    for (int i = wid; i < 128; i += 8) {
        int e = e0 + i;
        bool valid = e < NE;
        int r = valid ? erow[e] : 0;
        int c = valid ? ecol[e] : 0;
        if (lane == 0) sRow[i] = valid ? r : -1;
        if (lane < 3) {
            float d = valid ? (g_coord[r * 3 + lane] - g_coord[c * 3 + lane]) : 0.0f;
            sD[i * 4 + lane] = d;
        }
        __syncwarp();
        float d0 = sD[i * 4], d1 = sD[i * 4 + 1], d2 = sD[i * 4 + 2];
        float radial = d0 * d0 + d1 * d1 + d2 * d2;
        float ea = valid ? __ldg(&eattr[e]) : 0.0f;
        float4 a = __ldg(reinterpret_cast<const float4*>(&g_hr[(size_t)r * 128 + lane * 4]));
        float4 b = __ldg(reinterpret_cast<const float4*>(&g_hc[(size_t)c * 128 + lane * 4]));
        float4 wr = *(const float4*)&sWR[lane * 4];
        float4 we = *(const float4*)&sWE[lane * 4];
        float4 bb = *(const float4*)&sB1[lane * 4];
        float vx = silu_f(a.x + b.x + radial * wr.x + ea * we.x + bb.x);
        float vy = silu_f(a.y + b.y + radial * wr.y + ea * we.y + bb.y);
        float vz = silu_f(a.z + b.z + radial * wr.z + ea * we.z + bb.z);
        float vw = silu_f(a.w + b.w + radial * wr.w + ea * we.w + bb.w);
        uint32_t h0, l0, h1, l1;
        bf16_split2(vx, vy, h0, l0);
        bf16_split2(vz, vw, h1, l1);
        uint32_t off = (uint32_t)(i * PITCH_B + lane * 8);
        *(uint32_t*)(sb + OFF_AHI + off)     = h0;
        *(uint32_t*)(sb + OFF_AHI + off + 4) = h1;
        *(uint32_t*)(sb + OFF_ALO + off)     = l0;
        *(uint32_t*)(sb + OFF_ALO + off + 4) = l1;
    }
    __syncthreads();

    const int mrow0 = (wid >> 1) * 32;
    const int ncol0 = (wid & 1) * 64;
    const int rb = lane >> 2;
    float acc[2][8][4];

    // GEMM2: D2 = m1 @ W2
    mma_gemm3(sb, OFF_AHI, OFF_ALO, OFF_BHI, OFF_BLO, acc, mrow0, ncol0, lane);
    __syncthreads();   // all warps done reading A/B before overwrite

    // epilogue2: m = silu(D2 + b2); magg atomics; m -> A_hi/A_lo
    {
#pragma unroll
        for (int mt = 0; mt < 2; mt++) {
            int r0 = mrow0 + mt * 16 + rb;
            int r1 = r0 + 8;
            int node0 = sRow[r0], node1 = sRow[r1];
#pragma unroll
            for (int nt = 0; nt < 8; nt++) {
                int c = ncol0 + nt * 8 + (lane & 3) * 2;
                float v0 = silu_f(acc[mt][nt][0] + sB2[c]);
                float v1 = silu_f(acc[mt][nt][1] + sB2[c + 1]);
                float v2 = silu_f(acc[mt][nt][2] + sB2[c]);
                float v3 = silu_f(acc[mt][nt][3] + sB2[c + 1]);
                if (node0 >= 0) {
                    atomicAdd(&g_magg[(size_t)node0 * 128 + c],     v0);
                    atomicAdd(&g_magg[(size_t)node0 * 128 + c + 1], v1);
                }
                if (node1 >= 0) {
                    atomicAdd(&g_magg[(size_t)node1 * 128 + c],     v2);
                    atomicAdd(&g_magg[(size_t)node1 * 128 + c + 1], v3);
                }
                uint32_t h01, l01, h23, l23;
                bf16_split2(v0, v1, h01, l01);
                bf16_split2(v2, v3, h23, l23);
                uint32_t o0 = (uint32_t)(r0 * PITCH_B + c * 2);
                uint32_t o1 = (uint32_t)(r1 * PITCH_B + c * 2);
                *(uint32_t*)(sb + OFF_AHI + o0) = h01;
                *(uint32_t*)(sb + OFF_ALO + o0) = l01;
                *(uint32_t*)(sb + OFF_AHI + o1) = h23;
                *(uint32_t*)(sb + OFF_ALO + o1) = l23;
            }
        }
    }
    // B images for GEMM3 (Wc1)
    {
        const uint4* srcH = (const uint4*)(g_wpack + (size_t)((layer * 2 + 1) * 2 + 0) * 17408);
        const uint4* srcL = (const uint4*)(g_wpack + (size_t)((layer * 2 + 1) * 2 + 1) * 17408);
        uint4* dstH = (uint4*)(sb + OFF_BHI);
        uint4* dstL = (uint4*)(sb + OFF_BLO);
        for (int j = tid; j < 2176; j += 256) { dstH[j] = __ldg(&srcH[j]); dstL[j] = __ldg(&srcL[j]); }
    }
    __syncthreads();

    // GEMM3: D3 = m @ Wc1
    mma_gemm3(sb, OFF_AHI, OFF_ALO, OFF_BHI, OFF_BLO, acc, mrow0, ncol0, lane);

    // epilogue3: p = silu(D3 + bc1); cw = p . Wc2 ; coord agg atomics
    {
        float ps[4] = {0.f, 0.f, 0.f, 0.f};   // [mt*2 + (r0/r1)]
#pragma unroll
        for (int mt = 0; mt < 2; mt++) {
#pragma unroll
            for (int nt = 0; nt < 8; nt++) {
                int c = ncol0 + nt * 8 + (lane & 3) * 2;
                float p0 = silu_f(acc[mt][nt][0] + sBC[c]);
                float p1 = silu_f(acc[mt][nt][1] + sBC[c + 1]);
                float p2 = silu_f(acc[mt][nt][2] + sBC[c]);
                float p3 = silu_f(acc[mt][nt][3] + sBC[c + 1]);
                ps[mt * 2 + 0] = fmaf(p0, sWC[c], fmaf(p1, sWC[c + 1], ps[mt * 2 + 0]));
                ps[mt * 2 + 1] = fmaf(p2, sWC[c], fmaf(p3, sWC[c + 1], ps[mt * 2 + 1]));
            }
        }
#pragma unroll
        for (int j = 0; j < 4; j++) {
            ps[j] += __shfl_xor_sync(0xffffffffu, ps[j], 1);
            ps[j] += __shfl_xor_sync(0xffffffffu, ps[j], 2);
        }
        if ((lane & 3) == 0) {
            int ng = wid & 1;
#pragma unroll
            for (int mt = 0; mt < 2; mt++) {
                int r0 = mrow0 + mt * 16 + rb;
                sCW[r0 * 2 + ng]       = ps[mt * 2 + 0];
                sCW[(r0 + 8) * 2 + ng] = ps[mt * 2 + 1];
            }
        }
        __syncthreads();
        if (tid < 128) {
            int node = sRow[tid];
            if (node >= 0) {
                float cw = sCW[tid * 2] + sCW[tid * 2 + 1];
                atomicAdd(&g_cagg[node * 3 + 0], sD[tid * 4 + 0] * cw);
                atomicAdd(&g_cagg[node * 3 + 1], sD[tid * 4 + 1] * cw);
                atomicAdd(&g_cagg[node * 3 + 2], sD[tid * 4 + 2] * cw);
            }
        }
    }
}

// ---------------- node update (scalar FFMA2) ----------------
#define NODE_SMEM_F (64 * 260 + 64 * 132 + 32 * 128)

__global__ void __launch_bounds__(256) node_kernel(
    const float* __restrict__ W1, const float* __restrict__ b1,
    const float* __restrict__ W2, const float* __restrict__ b2)
{
    extern __shared__ float sm[];
    float* sNF = sm;
    float* sA  = sNF + 64 * 260;
    float* sW  = sA + 64 * 132;

    const int tid = threadIdx.x;
    const int warp = tid >> 5, lane = tid & 31;
    const int n0 = blockIdx.x * 64;

    if (tid < 192) {
        int i = tid / 3, d = tid - i * 3;
        int node = n0 + i;
        if (node < NN)
            g_coord[node * 3 + d] += g_cagg[node * 3 + d] / fmaxf(g_deg[node], 1.0f);
    }

    for (int i = warp; i < 64; i += 8) {
        int node = n0 + i;
        if (node < NN) {
            ((float4*)&sNF[i * 260])[lane] =
                *(const float4*)&g_h[(size_t)node * 128 + lane * 4];
            ((float4*)&sNF[i * 260 + 128])[lane] =
                *(const float4*)&g_magg[(size_t)node * 128 + lane * 4];
        } else {
            ((float4*)&sNF[i * 260])[lane]       = make_float4(0.f, 0.f, 0.f, 0.f);
            ((float4*)&sNF[i * 260 + 128])[lane] = make_float4(0.f, 0.f, 0.f, 0.f);
        }
    }

    const int tr = tid >> 5, tc = tid & 31;
    float acc[8][4];

    gemm_tile64(sNF, 260, W1, 256, sW, acc);
    {
        float4 bb = *(const float4*)&b1[tc * 4];
#pragma unroll
        for (int i = 0; i < 8; i++) {
            float4 v;
            v.x = silu_f(acc[i][0] + bb.x);
            v.y = silu_f(acc[i][1] + bb.y);
            v.z = silu_f(acc[i][2] + bb.z);
            v.w = silu_f(acc[i][3] + bb.w);
            *(float4*)&sA[(tr * 8 + i) * 132 + tc * 4] = v;
        }
    }
    __syncthreads();

    gemm_tile64(sA, 132, W2, 128, sW, acc);
    {
        float4 bb = *(const float4*)&b2[tc * 4];
#pragma unroll
        for (int i = 0; i < 8; i++) {
            int node = n0 + tr * 8 + i;
            if (node < NN) {
                float4 hv = *(const float4*)&sNF[(tr * 8 + i) * 260 + tc * 4];
                float4 o;
                o.x = hv.x + acc[i][0] + bb.x;
                o.y = hv.y + acc[i][1] + bb.y;
                o.z = hv.z + acc[i][2] + bb.z;
                o.w = hv.w + acc[i][3] + bb.w;
                *(float4*)&g_h[(size_t)node * 128 + tc * 4] = o;
            }
        }
    }
}

// ---------------- emb_out + graph pooling ----------------
#define POOL_SMEM_F (64 * 132 + 32 * 128)

__global__ void __launch_bounds__(256) embpool_kernel(
    const int* __restrict__ batch,
    const float* __restrict__ W, const float* __restrict__ b)
{
    extern __shared__ float sm[];
    float* sH = sm;
    float* sW = sH + 64 * 132;

    const int tid = threadIdx.x;
    const int warp = tid >> 5, lane = tid & 31;
    const int n0 = blockIdx.x * 64;

    for (int i = warp; i < 64; i += 8) {
        int node = n0 + i;
        ((float4*)&sH[i * 132])[lane] = (node < NN)
            ? *(const float4*)&g_h[(size_t)node * 128 + lane * 4]
            : make_float4(0.f, 0.f, 0.f, 0.f);
    }

    const int tr = tid >> 5, tc = tid & 31;
    float acc[8][4];
    gemm_tile64(sH, 132, W, 128, sW, acc);

    float4 bb = *(const float4*)&b[tc * 4];
#pragma unroll
    for (int i = 0; i < 8; i++) {
        int node = n0 + tr * 8 + i;
        if (node < NN) {
            int g = batch[node];
            float* pp = &g_pool[g * 128 + tc * 4];
            atomicAdd(pp + 0, acc[i][0] + bb.x);
            atomicAdd(pp + 1, acc[i][1] + bb.y);
            atomicAdd(pp + 2, acc[i][2] + bb.z);
            atomicAdd(pp + 3, acc[i][3] + bb.w);
        }
    }
}

// ---------------- final FC ----------------
__global__ void final_kernel(const float* __restrict__ fcW,
                             const float* __restrict__ fcB,
                             float* __restrict__ out)
{
    __shared__ float sg[128];
    int c = threadIdx.x;
    for (int g = 0; g < NG; g++) {
        if (c < 128) sg[c] = g_pool[g * 128 + c] / fmaxf(g_cnt[g], 1.0f);
        __syncthreads();
        float a = fcB[c];
#pragma unroll 8
        for (int k = 0; k < 128; k++) a = fmaf(sg[k], fcW[k * 256 + c], a);
        out[g * 256 + c] = a;
        __syncthreads();
    }
}

// ---------------- launch ----------------
extern "C" void kernel_launch(void* const* d_in, const int* in_sizes, int n_in,
                              void* d_out, int out_size)
{
    const float* x        = (const float*)d_in[0];
    const int*   eidx     = (const int*)d_in[1];
    const float* coord_in = (const float*)d_in[2];
    const float* eattr    = (const float*)d_in[3];
    const int*   batch    = (const int*)d_in[4];
    const float* emb_in_w = (const float*)d_in[5];
    const float* emb_in_b = (const float*)d_in[6];
    const float* edge_w1  = (const float*)d_in[7];
    const float* edge_b1  = (const float*)d_in[8];
    const float* edge_w2  = (const float*)d_in[9];
    const float* edge_b2  = (const float*)d_in[10];
    const float* node_w1  = (const float*)d_in[11];
    const float* node_b1  = (const float*)d_in[12];
    const float* node_w2  = (const float*)d_in[13];
    const float* node_b2  = (const float*)d_in[14];
    const float* coord_w1 = (const float*)d_in[15];
    const float* coord_b1 = (const float*)d_in[16];
    const float* coord_w2 = (const float*)d_in[17];
    const float* emb_out_w= (const float*)d_in[18];
    const float* emb_out_b= (const float*)d_in[19];
    const float* fc_w     = (const float*)d_in[20];
    const float* fc_b     = (const float*)d_in[21];
    float* out = (float*)d_out;

    const int* erow = eidx;
    const int* ecol = eidx + NE;

    static bool attr_done = false;
    if (!attr_done) {
        cudaFuncSetAttribute(edge_mma_kernel, cudaFuncAttributeMaxDynamicSharedMemorySize,
                             EDGE_SMEM_BYTES);
        cudaFuncSetAttribute(node_kernel, cudaFuncAttributeMaxDynamicSharedMemorySize,
                             NODE_SMEM_F * 4);
        cudaFuncSetAttribute(embpool_kernel, cudaFuncAttributeMaxDynamicSharedMemorySize,
                             POOL_SMEM_F * 4);
        cudaFuncSetAttribute(hpre_kernel, cudaFuncAttributeMaxDynamicSharedMemorySize,
                             HPRE_SMEM_F * 4);
        attr_done = true;
    }

    const int edge_blocks = (NE + 127) / 128;     // 4688
    const int node_blocks = (NN + 63) / 64;       // 782

    setup1_kernel<<<586, 256>>>(coord_in, edge_w2, coord_w1);
    mega2_kernel<<<((size_t)NN * HID + 255) / 256, 256>>>(erow, batch, x, emb_in_w, emb_in_b);

    for (int l = 0; l < 3; l++) {
        if (l > 0)
            zero_layer_kernel<<<((size_t)NN * HID + 255) / 256, 256>>>();
        hpre_kernel<<<node_blocks, 256, HPRE_SMEM_F * 4>>>(edge_w1 + (size_t)l * 258 * 128);
        edge_mma_kernel<<<edge_blocks, 256, EDGE_SMEM_BYTES>>>(
            erow, ecol, eattr,
            edge_w1 + (size_t)l * 258 * 128, edge_b1 + l * 128,
            edge_b2 + l * 128, coord_b1 + l * 128, coord_w2 + (size_t)l * 128, l);
        node_kernel<<<node_blocks, 256, NODE_SMEM_F * 4>>>(
            node_w1 + (size_t)l * 256 * 128, node_b1 + l * 128,
            node_w2 + (size_t)l * 128 * 128, node_b2 + l * 128);
    }

    embpool_kernel<<<node_blocks, 256, POOL_SMEM_F * 4>>>(batch, emb_out_w, emb_out_b);
    final_kernel<<<1, 256>>>(fc_w, fc_b, out);
}